// round 1
// baseline (speedup 1.0000x reference)
#include <cuda_runtime.h>
#include <math.h>

#define N_NODES 10000
#define N_EDGES 160000
#define BATCH 4
#define T_STEPS 16
#define HID 64
#define M_ROWS (N_NODES*BATCH)   // 40000
#define KDIM 208                 // 195 real channels padded to 208

// ---------------- scratch (device globals: allocation-free rule) ----------------
__device__ float g_h [M_ROWS*HID];
__device__ float g_z [M_ROWS*HID];
__device__ float g_rh[M_ROWS*HID];
__device__ float g_U [(size_t)M_ROWS*KDIM];      // 33.3 MB
__device__ float g_xt[M_ROWS];
__device__ float g_deg_out[N_NODES], g_deg_in[N_NODES];
__device__ int   g_cntF[N_NODES], g_cntB[N_NODES];
__device__ int   g_offF[N_NODES+1], g_offB[N_NODES+1];
__device__ int   g_srcF[N_EDGES], g_srcB[N_EDGES];
__device__ float g_wF[N_EDGES],  g_wB[N_EDGES];
__device__ float g_Wzr[KDIM*128], g_Wh[KDIM*64];
__device__ float g_bzr[128], g_bh[64];

// ---------------- preprocessing ----------------
__global__ void zero_pre() {
    int i = blockIdx.x*blockDim.x + threadIdx.x;
    if (i < N_NODES) { g_deg_out[i]=0.f; g_deg_in[i]=0.f; g_cntF[i]=0; g_cntB[i]=0; }
}
__global__ void zero_h() {
    int i = blockIdx.x*blockDim.x + threadIdx.x;
    if (i < M_ROWS*HID) g_h[i] = 0.f;
}
__global__ void edge_deg(const int* __restrict__ ei, const float* __restrict__ ew) {
    int e = blockIdx.x*blockDim.x + threadIdx.x;
    if (e >= N_EDGES) return;
    int r = ei[e], c = ei[N_EDGES + e];
    float w = ew[e];
    atomicAdd(&g_deg_out[r], w);
    atomicAdd(&g_deg_in [c], w);
    atomicAdd(&g_cntF[r], 1);
    atomicAdd(&g_cntB[c], 1);
}
// single-block exclusive scan over both count arrays (also resets counts to 0)
__global__ void scan_kernel() {
    __shared__ int sb[1024];
    int t = threadIdx.x;
    for (int pass = 0; pass < 2; pass++) {
        int*       cnt = pass == 0 ? g_cntF : g_cntB;
        int*       off = pass == 0 ? g_offF : g_offB;
        int carry = 0;
        for (int base = 0; base < N_NODES; base += 1024) {
            int v = (base + t < N_NODES) ? cnt[base + t] : 0;
            sb[t] = v; __syncthreads();
            for (int o = 1; o < 1024; o <<= 1) {
                int y = (t >= o) ? sb[t - o] : 0;
                __syncthreads();
                sb[t] += y;
                __syncthreads();
            }
            if (base + t < N_NODES) { off[base + t] = carry + sb[t] - v; cnt[base + t] = 0; }
            carry += sb[1023];
            __syncthreads();
        }
        if (t == 0) off[N_NODES] = carry;
        __syncthreads();
    }
}
__global__ void edge_fill(const int* __restrict__ ei, const float* __restrict__ ew) {
    int e = blockIdx.x*blockDim.x + threadIdx.x;
    if (e >= N_EDGES) return;
    int r = ei[e], c = ei[N_EDGES + e];
    float w = ew[e];
    float dof = g_deg_out[r];
    float cf = (dof > 0.f) ? w / dof : 0.f;
    int p = g_offF[r] + atomicAdd(&g_cntF[r], 1);
    g_srcF[p] = c; g_wF[p] = cf;
    float din = g_deg_in[c];
    float cb = (din > 0.f) ? w / din : 0.f;
    int q = g_offB[c] + atomicAdd(&g_cntB[c], 1);
    g_srcB[q] = r; g_wB[q] = cb;
}

// W layout: [dir][order][c(65)][j(64)] -> ((d*2+o)*65+c)*64+j
__device__ __forceinline__ float wval(const float* W, int c, int j) {
    if (c >= 195) return 0.f;
    if (c < 65)  return W[(0*65 + c)*64 + j] + W[(2*65 + c)*64 + j];   // W[0][0]+W[1][0]
    if (c < 130) return W[(1*65 + (c-65))*64 + j];                      // W[0][1]
    return W[(3*65 + (c-130))*64 + j];                                  // W[1][1]
}
__global__ void prep_weights(const float* __restrict__ W_z, const float* __restrict__ b_z,
                             const float* __restrict__ W_r, const float* __restrict__ b_r,
                             const float* __restrict__ W_h, const float* __restrict__ b_h) {
    int tid = blockIdx.x*blockDim.x + threadIdx.x;
    if (tid < 128) g_bzr[tid] = (tid < 64) ? b_z[tid] : b_r[tid - 64];
    if (tid < 64)  g_bh[tid]  = b_h[tid];
    if (tid < KDIM*128) {
        int c = tid / 128, j = tid % 128;
        const float* W = (j < 64) ? W_z : W_r;
        g_Wzr[tid] = wval(W, c, j & 63);
    }
    int t2 = tid - KDIM*128;
    if (t2 >= 0 && t2 < KDIM*64) {
        int c = t2 / 64, j = t2 % 64;
        g_Wh[t2] = wval(W_h, c, j);
    }
}

// per-step: xt[n*B+b] = x_dis[b][t][n]
__global__ void kx_kernel(const float* __restrict__ x_dis, int t) {
    int i = blockIdx.x*blockDim.x + threadIdx.x;
    if (i < M_ROWS) {
        int n = i >> 2, b = i & 3;
        g_xt[i] = x_dis[(size_t)(b*T_STEPS + t)*N_NODES + n];
    }
}

// ---------------- per-step aggregation: builds U rows ----------------
// U channels: [0]=x, [1..64]=h(or rh), [65]=aggF_x, [66..129]=aggF_h,
//             [130]=aggB_x, [131..194]=aggB_h, [195..207]=0 (pad)
// full=1: first pass (uses g_h, also writes x / aggX / pads)
// full=0: second pass (uses g_rh; x, aggX, pads kept from pass 1)
__global__ void agg_kernel(int full) {
    const float* __restrict__ hsrc = full ? g_h : g_rh;
    int n   = blockIdx.x;
    int tid = threadIdx.x;
    int b = tid >> 6, c = tid & 63;
    int row = n*BATCH + b;
    float* Urow = g_U + (size_t)row*KDIM;

    Urow[1 + c] = hsrc[row*HID + c];
    if (full) {
        if (c == 0)  Urow[0] = g_xt[row];
        if (c >= 51) Urow[144 + c] = 0.f;   // pads 195..207
    }

    __shared__ int   s_src[256];
    __shared__ float s_w[256];

    for (int dir = 0; dir < 2; dir++) {
        const int*   off = dir == 0 ? g_offF : g_offB;
        const int*   src = dir == 0 ? g_srcF : g_srcB;
        const float* ww  = dir == 0 ? g_wF   : g_wB;
        int e0 = off[n], e1 = off[n + 1];
        float accH = 0.f, accX = 0.f;
        for (int base = e0; base < e1; base += 256) {
            int len = min(256, e1 - base);
            __syncthreads();
            if (tid < len) { s_src[tid] = src[base + tid]; s_w[tid] = ww[base + tid]; }
            __syncthreads();
            int i = 0;
            for (; i + 4 <= len; i += 4) {
                int s0 = s_src[i], s1 = s_src[i+1], s2 = s_src[i+2], s3 = s_src[i+3];
                float w0 = s_w[i], w1 = s_w[i+1], w2 = s_w[i+2], w3 = s_w[i+3];
                float v0 = hsrc[(s0*BATCH + b)*HID + c];
                float v1 = hsrc[(s1*BATCH + b)*HID + c];
                float v2 = hsrc[(s2*BATCH + b)*HID + c];
                float v3 = hsrc[(s3*BATCH + b)*HID + c];
                accH += w0*v0 + w1*v1 + w2*v2 + w3*v3;
                if (full && c == 0) {
                    accX += w0*g_xt[s0*BATCH + b] + w1*g_xt[s1*BATCH + b]
                          + w2*g_xt[s2*BATCH + b] + w3*g_xt[s3*BATCH + b];
                }
            }
            for (; i < len; i++) {
                int s = s_src[i]; float w = s_w[i];
                accH += w * hsrc[(s*BATCH + b)*HID + c];
                if (full && c == 0) accX += w * g_xt[s*BATCH + b];
            }
        }
        int chbase = dir == 0 ? 65 : 130;
        Urow[chbase + 1 + c] = accH;
        if (full && c == 0) Urow[chbase] = accX;
    }
}

// ---------------- GEMM: [M x 208] @ [208 x NOUT], fused GRU epilogues ----------------
// NOUT=128 (z,r gates): z = sigmoid, rh = sigmoid(r)*h
// NOUT=64  (c gate):    h = z*h + (1-z)*tanh(c)
template<int NOUT, int NT>
__global__ void __launch_bounds__(NT) gemm_kernel() {
    constexpr int BM = 64, BK = 16;
    constexpr int CG = NOUT / 4;         // col groups of 4
    constexpr int RPT = 8;               // rows per thread
    __shared__ float Us[BM][BK];
    __shared__ float Ws[BK][NOUT];
    int tid = threadIdx.x;
    int tx = tid % CG, ty = tid / CG;    // ty in [0,8)
    int rowBase = blockIdx.x * BM;
    const float* __restrict__ Wg = (NOUT == 128) ? g_Wzr : g_Wh;

    float acc[RPT][4];
#pragma unroll
    for (int r = 0; r < RPT; r++)
#pragma unroll
        for (int q = 0; q < 4; q++) acc[r][q] = 0.f;

    for (int k0 = 0; k0 < KDIM; k0 += BK) {
#pragma unroll
        for (int idx = tid; idx < BM*BK/4; idx += NT) {
            int r = idx >> 2, s = idx & 3;
            *(float4*)&Us[r][s*4] =
                *(const float4*)(g_U + (size_t)(rowBase + r)*KDIM + k0 + s*4);
        }
#pragma unroll
        for (int idx = tid; idx < BK*NOUT/4; idx += NT) {
            int rr = idx / (NOUT/4), ss = idx % (NOUT/4);
            *(float4*)&Ws[rr][ss*4] = *(const float4*)(Wg + (size_t)(k0 + rr)*NOUT + ss*4);
        }
        __syncthreads();
#pragma unroll
        for (int kk = 0; kk < BK; kk++) {
            float4 wv = *(float4*)&Ws[kk][tx*4];
#pragma unroll
            for (int r = 0; r < RPT; r++) {
                float u = Us[ty*RPT + r][kk];
                acc[r][0] += u*wv.x; acc[r][1] += u*wv.y;
                acc[r][2] += u*wv.z; acc[r][3] += u*wv.w;
            }
        }
        __syncthreads();
    }

    int jbase = tx * 4;
#pragma unroll
    for (int r = 0; r < RPT; r++) {
        int row = rowBase + ty*RPT + r;
        if (NOUT == 128) {
            if (jbase < 64) {
#pragma unroll
                for (int q = 0; q < 4; q++) {
                    int j = jbase + q;
                    float zv = 1.f / (1.f + __expf(-(acc[r][q] + g_bzr[j])));
                    g_z[row*HID + j] = zv;
                }
            } else {
#pragma unroll
                for (int q = 0; q < 4; q++) {
                    int j = jbase + q, jr = j - 64;
                    float rv = 1.f / (1.f + __expf(-(acc[r][q] + g_bzr[j])));
                    g_rh[row*HID + jr] = rv * g_h[row*HID + jr];
                }
            }
        } else {
#pragma unroll
            for (int q = 0; q < 4; q++) {
                int j = jbase + q;
                float cv = tanhf(acc[r][q] + g_bh[j]);
                float zv = g_z[row*HID + j];
                float hv = g_h[row*HID + j];
                g_h[row*HID + j] = zv*hv + (1.f - zv)*cv;
            }
        }
    }
}

// ---------------- readout (node 0 only) ----------------
__global__ void readout_kernel(const float* __restrict__ W1, const float* __restrict__ b1,
                               const float* __restrict__ W2, const float* __restrict__ b2,
                               float* __restrict__ out) {
    int tid = threadIdx.x;
    int b = tid >> 6, j = tid & 63;
    float acc = b1[j];
#pragma unroll
    for (int c = 0; c < HID; c++)
        acc += g_h[b*HID + c] * W1[c*HID + j];   // rows 0..3 of g_h are node 0
    float v = fmaxf(acc, 0.f) * W2[j];
#pragma unroll
    for (int o = 16; o > 0; o >>= 1) v += __shfl_down_sync(0xffffffff, v, o);
    __shared__ float part[8];
    if ((tid & 31) == 0) part[tid >> 5] = v;
    __syncthreads();
    if (j == 0) out[b] = part[b*2] + part[b*2 + 1] + b2[0];
}

// ---------------- launch ----------------
extern "C" void kernel_launch(void* const* d_in, const int* in_sizes, int n_in,
                              void* d_out, int out_size) {
    const float* x_dis = (const float*)d_in[0];
    const int*   ei    = (const int*)  d_in[1];
    const float* ew    = (const float*)d_in[2];
    const float* W_z   = (const float*)d_in[3];
    const float* b_z   = (const float*)d_in[4];
    const float* W_r   = (const float*)d_in[5];
    const float* b_r   = (const float*)d_in[6];
    const float* W_h   = (const float*)d_in[7];
    const float* b_h   = (const float*)d_in[8];
    const float* W_ro1 = (const float*)d_in[9];
    const float* b_ro1 = (const float*)d_in[10];
    const float* W_ro2 = (const float*)d_in[11];
    const float* b_ro2 = (const float*)d_in[12];
    float* out = (float*)d_out;

    zero_pre <<<(N_NODES + 255)/256, 256>>>();
    zero_h   <<<(M_ROWS*HID + 511)/512, 512>>>();
    edge_deg <<<(N_EDGES + 255)/256, 256>>>(ei, ew);
    scan_kernel<<<1, 1024>>>();
    edge_fill<<<(N_EDGES + 255)/256, 256>>>(ei, ew);
    prep_weights<<<(KDIM*192 + 255)/256, 256>>>(W_z, b_z, W_r, b_r, W_h, b_h);

    for (int t = 0; t < T_STEPS; t++) {
        kx_kernel<<<(M_ROWS + 255)/256, 256>>>(x_dis, t);
        agg_kernel<<<N_NODES, 256>>>(1);
        gemm_kernel<128, 256><<<M_ROWS/64, 256>>>();
        agg_kernel<<<N_NODES, 256>>>(0);
        gemm_kernel<64, 128><<<M_ROWS/64, 128>>>();
    }
    readout_kernel<<<1, 256>>>(W_ro1, b_ro1, W_ro2, b_ro2, out);
}